// round 7
// baseline (speedup 1.0000x reference)
#include <cuda_runtime.h>
#include <cstdint>

// Problem dims
#define BB 4
#define MM 512
#define NN 512
#define KK 128

// Decoded scratch, k-major per batch: g_dA[b][k][m], g_dB[b][k][n]
__device__ __align__(16) float g_dA[BB * KK * MM];
__device__ __align__(16) float g_dB[BB * KK * NN];
// fp32 GEMM result scratch: g_C[b][m][n]
__device__ __align__(16) float g_C[BB * MM * NN];

// ---------------------------------------------------------------------------
// Kernel 1: decode 8-pulse FP8 E4M3 codes -> fp32, k-major output via smem
// transpose. DEC_R=8 rows per CTA -> grid=512 CTAs (~3.5/SM) for MLP:
// round 5 showed grid=128 left decode latency-bound at occ=12.8%.
// Input: 32B/thread contiguous (2x float4). Output: 32B aligned per k-row.
// Exact decode: power-of-two via exponent field; (1+m/8) exact.
// ---------------------------------------------------------------------------
#define DEC_R 8

__global__ __launch_bounds__(256) void decode_kernel(const float4* __restrict__ inA,
                                                     const float4* __restrict__ inB) {
    __shared__ float s[KK][DEC_R + 1];  // pad -> conflict-free

    const int blk = blockIdx.x;                 // 0..511
    const bool isB = blk >= 256;
    const int sub = isB ? (blk - 256) : blk;    // 0..255
    const int b  = sub >> 6;                    // batch (64 row-blocks/batch)
    const int r0 = (sub & 63) * DEC_R;          // row-block start

    const float4* __restrict__ in = isB ? inB : inA;
    float* __restrict__ outp = isB ? g_dB : g_dA;

    const int tid = threadIdx.x;
    const long gbase = ((long)(b * MM + r0)) * KK;

    // Decode 4 codes per thread; input fully coalesced.
#pragma unroll
    for (int j = 0; j < 4; j++) {
        int c = j * 256 + tid;           // 0..1023: r_local = c>>7, k = c&127
        float4 p0 = in[(gbase + c) * 2];
        float4 p1 = in[(gbase + c) * 2 + 1];

        float ef = p0.y * 8.0f + p0.z * 4.0f + p0.w * 2.0f + p1.x;
        float mf = p1.y * 4.0f + p1.z * 2.0f + p1.w;
        int e = (int)ef;

        float mag;
        if (e > 0) {
            mag = __uint_as_float((unsigned)(e + 120) << 23) * (1.0f + mf * 0.125f);
        } else {
            mag = mf * (1.0f / 512.0f);  // subnormal: m * 2^-9
        }
        float val = (p0.x > 0.5f) ? -mag : mag;

        s[c & (KK - 1)][c >> 7] = val;
    }
    __syncthreads();

    // Write k-major: 128 k-rows x 2 float4 = 256 float4, one per thread.
    {
        int k  = tid >> 1;
        int r4 = (tid & 1) * 4;
        float4 v;
        v.x = s[k][r4 + 0];
        v.y = s[k][r4 + 1];
        v.z = s[k][r4 + 2];
        v.w = s[k][r4 + 3];
        *(float4*)&outp[(b * KK + k) * MM + r0 + r4] = v;
    }
}

// ---------------------------------------------------------------------------
// Kernel 2: batched GEMM C = A @ B^T with STRICT sequential-k fp32 FMA
// accumulation (single accumulator per element, k ascending). Writes plain
// fp32 C to scratch, coalesced. DO NOT reassociate (bit-exactness).
// ---------------------------------------------------------------------------
#define BMT 64
#define BNT 64
#define KCH 64

__global__ __launch_bounds__(256) void gemm_kernel() {
    __shared__ float As[KCH][BMT];
    __shared__ float Bs[KCH][BNT];

    const int b   = blockIdx.z;
    const int tm0 = blockIdx.y * BMT;
    const int tn0 = blockIdx.x * BNT;
    const int tid = threadIdx.x;
    const int tx  = tid & 15;
    const int ty  = tid >> 4;

    const float* __restrict__ Ab = g_dA + b * KK * MM;
    const float* __restrict__ Bb = g_dB + b * KK * NN;

    float acc[4][4];
#pragma unroll
    for (int i = 0; i < 4; i++)
#pragma unroll
        for (int j = 0; j < 4; j++) acc[i][j] = 0.0f;

#pragma unroll
    for (int k0 = 0; k0 < KK; k0 += KCH) {
#pragma unroll
        for (int i = 0; i < 4; i++) {
            int r  = i * 16 + (tid >> 4);
            int c4 = (tid & 15) * 4;
            *(float4*)&As[r][c4] = *(const float4*)&Ab[(k0 + r) * MM + tm0 + c4];
            *(float4*)&Bs[r][c4] = *(const float4*)&Bb[(k0 + r) * NN + tn0 + c4];
        }
        __syncthreads();

#pragma unroll
        for (int k = 0; k < KCH; k++) {
            float4 a4 = *(const float4*)&As[k][ty * 4];
            float4 b4 = *(const float4*)&Bs[k][tx * 4];
            float av[4] = {a4.x, a4.y, a4.z, a4.w};
            float bv[4] = {b4.x, b4.y, b4.z, b4.w};
#pragma unroll
            for (int i = 0; i < 4; i++)
#pragma unroll
                for (int j = 0; j < 4; j++)
                    acc[i][j] = fmaf(av[i], bv[j], acc[i][j]);
        }
        __syncthreads();
    }

#pragma unroll
    for (int i = 0; i < 4; i++) {
        int m = tm0 + ty * 4 + i;
        float4 v = make_float4(acc[i][0], acc[i][1], acc[i][2], acc[i][3]);
        *(float4*)&g_C[(b * MM + m) * NN + tn0 + tx * 4] = v;
    }
}

// ---------------------------------------------------------------------------
// Kernel 3: encode expand. One thread per TWO consecutive output float4s
// (8 bit planes). Warp writes 1KB contiguous. Streaming stores (.cs) keep
// the 4MB C L2-resident under the 128MB output stream.
// ---------------------------------------------------------------------------
__global__ __launch_bounds__(256) void encode_kernel(float4* __restrict__ out,
                                                     unsigned n2) {
    unsigned t = blockIdx.x * 256u + threadIdx.x;  // pair index
    if (t >= n2) return;
    unsigned u = __float_as_uint(__ldg(&g_C[t >> 2]));
    unsigned q = (t & 3u) * 2u;
    unsigned s0 = 28u - 4u * q;
    float4 v0, v1;
    v0.x = ((u >> (s0 + 3)) & 1u) ? 1.0f : 0.0f;
    v0.y = ((u >> (s0 + 2)) & 1u) ? 1.0f : 0.0f;
    v0.z = ((u >> (s0 + 1)) & 1u) ? 1.0f : 0.0f;
    v0.w = ((u >> (s0 + 0)) & 1u) ? 1.0f : 0.0f;
    unsigned s1 = s0 - 4u;
    v1.x = ((u >> (s1 + 3)) & 1u) ? 1.0f : 0.0f;
    v1.y = ((u >> (s1 + 2)) & 1u) ? 1.0f : 0.0f;
    v1.z = ((u >> (s1 + 1)) & 1u) ? 1.0f : 0.0f;
    v1.w = ((u >> (s1 + 0)) & 1u) ? 1.0f : 0.0f;
    __stcs(&out[2 * t], v0);
    __stcs(&out[2 * t + 1], v1);
}

extern "C" void kernel_launch(void* const* d_in, const int* in_sizes, int n_in,
                              void* d_out, int out_size) {
    const float4* A = (const float4*)d_in[0];
    const float4* B = (const float4*)d_in[1];

    decode_kernel<<<512, 256>>>(A, B);

    dim3 grid(NN / BNT, MM / BMT, BB);  // (8, 8, 4)
    gemm_kernel<<<grid, 256>>>();

    unsigned n2 = (unsigned)(out_size / 8);  // float4 pairs: 4194304
    encode_kernel<<<(n2 + 255) / 256, 256>>>((float4*)d_out, n2);
}

// round 9
// speedup vs baseline: 1.2349x; 1.2349x over previous
#include <cuda_runtime.h>
#include <cstdint>

// Problem dims
#define BB 4
#define MM 512
#define NN 512
#define KK 128

// Decoded scratch, k-major per batch: g_dA[b][k][m], g_dB[b][k][n]
__device__ __align__(16) float g_dA[BB * KK * MM];
__device__ __align__(16) float g_dB[BB * KK * NN];

// ---------------------------------------------------------------------------
// Kernel 1: decode 8-pulse FP8 E4M3 codes -> fp32, k-major output via smem
// transpose. Grid=512 CTAs for MLP (R7: occ 41%, 6.9us).
// Exact decode: power-of-two via exponent field; (1+m/8) exact.
// ---------------------------------------------------------------------------
#define DEC_R 8

__global__ __launch_bounds__(256) void decode_kernel(const float4* __restrict__ inA,
                                                     const float4* __restrict__ inB) {
    __shared__ float s[KK][DEC_R + 1];  // pad -> conflict-free

    const int blk = blockIdx.x;                 // 0..511
    const bool isB = blk >= 256;
    const int sub = isB ? (blk - 256) : blk;    // 0..255
    const int b  = sub >> 6;                    // batch
    const int r0 = (sub & 63) * DEC_R;          // row-block start

    const float4* __restrict__ in = isB ? inB : inA;
    float* __restrict__ outp = isB ? g_dB : g_dA;

    const int tid = threadIdx.x;
    const long gbase = ((long)(b * MM + r0)) * KK;

#pragma unroll
    for (int j = 0; j < 4; j++) {
        int c = j * 256 + tid;           // r_local = c>>7, k = c&127
        float4 p0 = in[(gbase + c) * 2];
        float4 p1 = in[(gbase + c) * 2 + 1];

        float ef = p0.y * 8.0f + p0.z * 4.0f + p0.w * 2.0f + p1.x;
        float mf = p1.y * 4.0f + p1.z * 2.0f + p1.w;
        int e = (int)ef;

        float mag;
        if (e > 0) {
            mag = __uint_as_float((unsigned)(e + 120) << 23) * (1.0f + mf * 0.125f);
        } else {
            mag = mf * (1.0f / 512.0f);  // subnormal: m * 2^-9
        }
        float val = (p0.x > 0.5f) ? -mag : mag;

        s[c & (KK - 1)][c >> 7] = val;
    }
    __syncthreads();

    {
        int k  = tid >> 1;
        int r4 = (tid & 1) * 4;
        float4 v;
        v.x = s[k][r4 + 0];
        v.y = s[k][r4 + 1];
        v.z = s[k][r4 + 2];
        v.w = s[k][r4 + 3];
        *(float4*)&outp[(b * KK + k) * MM + r0 + r4] = v;
    }
}

// ---------------------------------------------------------------------------
// Kernel 2: FUSED batched GEMM + bit-plane encode.
// 32x32 C tile per CTA (grid=1024), 256 threads, 2x2 micro-tile.
// STRICT sequential-k fp32 FMA accumulation (single accumulator, k ascending)
// -- DO NOT reassociate; bit-exactness vs reference depends on this.
// After accumulation: stage C tile in smem, then encode+store 128KB per CTA
// with lane-contiguous STG.128 (thread t writes float4 row_base+t), __stcs.
// ---------------------------------------------------------------------------
#define BMT 32
#define BNT 32
#define KCH 64

__global__ __launch_bounds__(256) void gemm_encode_kernel(float4* __restrict__ out) {
    __shared__ float As[KCH][BMT];   // 8 KB
    __shared__ float Bs[KCH][BNT];   // 8 KB

    const int b   = blockIdx.z;
    const int tm0 = blockIdx.y * BMT;
    const int tn0 = blockIdx.x * BNT;
    const int tid = threadIdx.x;
    const int tx  = tid & 15;        // n pair selector (2 cols)
    const int ty  = tid >> 4;        // m pair selector (2 rows)

    const float* __restrict__ Ab = g_dA + b * KK * MM;
    const float* __restrict__ Bb = g_dB + b * KK * NN;

    float acc00 = 0.0f, acc01 = 0.0f, acc10 = 0.0f, acc11 = 0.0f;

#pragma unroll
    for (int k0 = 0; k0 < KK; k0 += KCH) {
        // Load 64k x 32 tiles of A and B: 512 float4 each / 256 threads = 2.
#pragma unroll
        for (int i = 0; i < 2; i++) {
            int w  = i * 256 + tid;
            int r  = w >> 3;
            int c4 = (w & 7) * 4;
            *(float4*)&As[r][c4] = *(const float4*)&Ab[(k0 + r) * MM + tm0 + c4];
            *(float4*)&Bs[r][c4] = *(const float4*)&Bb[(k0 + r) * NN + tn0 + c4];
        }
        __syncthreads();

        // Sequential over k (ascending), single accumulator per element.
#pragma unroll
        for (int k = 0; k < KCH; k++) {
            float2 a2 = *(const float2*)&As[k][ty * 2];
            float2 b2 = *(const float2*)&Bs[k][tx * 2];
            acc00 = fmaf(a2.x, b2.x, acc00);
            acc01 = fmaf(a2.x, b2.y, acc01);
            acc10 = fmaf(a2.y, b2.x, acc10);
            acc11 = fmaf(a2.y, b2.y, acc11);
        }
        __syncthreads();
    }

    // Stage C tile into smem (reuse As rows 0..31: 32x32 floats = 4 KB).
    float (*Cs)[BMT] = As;
    *(float2*)&Cs[ty * 2 + 0][tx * 2] = make_float2(acc00, acc01);
    *(float2*)&Cs[ty * 2 + 1][tx * 2] = make_float2(acc10, acc11);
    __syncthreads();

    // Encode + store. Output row (b, m): 512 n * 8 float4; this tile covers
    // [tn0, tn0+32) -> 256 contiguous float4 starting at row base.
    // Thread t handles n_local = t>>3, nibble q = t&7. Lanes contiguous.
    const unsigned base0 = ((unsigned)((b * MM + tm0) * NN + tn0)) * 8u;
    const unsigned q = (unsigned)(tid & 7);
    const unsigned s0 = 28u - 4u * q;        // bit pos of .w
    const int nl = tid >> 3;

#pragma unroll 4
    for (int ml = 0; ml < BMT; ml++) {
        unsigned u = __float_as_uint(Cs[ml][nl]);
        float4 v;
        v.x = ((u >> (s0 + 3)) & 1u) ? 1.0f : 0.0f;
        v.y = ((u >> (s0 + 2)) & 1u) ? 1.0f : 0.0f;
        v.z = ((u >> (s0 + 1)) & 1u) ? 1.0f : 0.0f;
        v.w = ((u >> (s0 + 0)) & 1u) ? 1.0f : 0.0f;
        __stcs(&out[base0 + (unsigned)ml * (NN * 8u) + (unsigned)tid], v);
    }
}

extern "C" void kernel_launch(void* const* d_in, const int* in_sizes, int n_in,
                              void* d_out, int out_size) {
    const float4* A = (const float4*)d_in[0];
    const float4* B = (const float4*)d_in[1];

    decode_kernel<<<512, 256>>>(A, B);

    dim3 grid(NN / BNT, MM / BMT, BB);  // (16, 16, 4) = 1024 CTAs
    gemm_encode_kernel<<<grid, 256>>>((float4*)d_out);
}